// round 15
// baseline (speedup 1.0000x reference)
#include <cuda_runtime.h>
#include <cuda_bf16.h>
#include <cuda_fp16.h>
#include <cstdint>
#include <type_traits>

#define D_DIM 1792
#define B_DIM 8192
#define NB 128
#define NBLK (D_DIM / NB)     // 14
#define NB2 256
#define NBLK2 (D_DIM / NB2)   // 7
#define MREM0 1536

// ---------------- fp32 scratch ----------------
__device__ __align__(16) float g_Vn   [ (size_t)D_DIM * D_DIM ];
__device__ __align__(16) float g_G    [ (size_t)D_DIM * D_DIM ];
__device__ __align__(16) float g_Tinv [ (size_t)NBLK * NB * NB ];
__device__ __align__(16) float g_Tinv2[ (size_t)NBLK2 * NB2 * NB2 ];

// ---------------- bf16 hi|lo scratch ----------------
__device__ __align__(16) __nv_bfloat16 g_Vn_hl    [ (size_t)D_DIM * 2 * D_DIM ];
__device__ __align__(16) __nv_bfloat16 g_G_hl     [ (size_t)D_DIM * 2 * D_DIM ];
__device__ __align__(16) __nv_bfloat16 g_Tinv2T_hl[ (size_t)NBLK2 * NB2 * 2 * NB2 ];

// ---------------- fp16 scratch ----------------
__device__ __align__(16) __half g_VnT_h2  [ (size_t)D_DIM * 2 * D_DIM ];   // hi|lo
__device__ __align__(16) __half g_RHST_h2 [ (size_t)D_DIM * 2 * D_DIM ];   // hi|lo
__device__ __align__(16) __half g_WtT_h2  [ (size_t)D_DIM * 2 * D_DIM ];   // hi|lo
__device__ __align__(16) __half g_Tinv2_h2[ (size_t)NBLK2 * NB2 * 2 * NB2 ]; // hi|lo
__device__ __align__(16) __half g_S_h     [ (size_t)(NBLK2 - 1) * MREM0 * NB2 ]; // single
__device__ __align__(16) __half g_P_h     [ (size_t)D_DIM * D_DIM ];
__device__ __align__(16) __half g_XT_h    [ (size_t)B_DIM * D_DIM ];

// ============================================================================
// helpers
// ============================================================================
__device__ __forceinline__ uint32_t smem_u32(const void* p) {
    uint32_t a;
    asm("{ .reg .u64 t; cvta.to.shared.u64 t, %1; cvt.u32.u64 %0, t; }"
        : "=r"(a) : "l"(p));
    return a;
}
__device__ __forceinline__ void cpa16(uint32_t s, const void* g) {
    asm volatile("cp.async.cg.shared.global [%0], [%1], 16;" :: "r"(s), "l"(g));
}
#define CPA_COMMIT() asm volatile("cp.async.commit_group;" ::: "memory")
#define CPA_WAIT(n)  asm volatile("cp.async.wait_group %0;" :: "n"(n) : "memory")

#define LDSM4(r0, r1, r2, r3, addr) \
    asm volatile("ldmatrix.sync.aligned.m8n8.x4.shared.b16 {%0,%1,%2,%3}, [%4];" \
        : "=r"(r0), "=r"(r1), "=r"(r2), "=r"(r3) : "r"(addr))

#define MMA_BF(d, a, b0, b1) \
    asm volatile("mma.sync.aligned.m16n8k16.row.col.f32.bf16.bf16.f32 " \
        "{%0,%1,%2,%3}, {%4,%5,%6,%7}, {%8,%9}, {%0,%1,%2,%3};" \
        : "+f"((d)[0]), "+f"((d)[1]), "+f"((d)[2]), "+f"((d)[3]) \
        : "r"((a)[0]), "r"((a)[1]), "r"((a)[2]), "r"((a)[3]), "r"(b0), "r"(b1))

#define MMA_FP(d, a, b0, b1) \
    asm volatile("mma.sync.aligned.m16n8k16.row.col.f32.f16.f16.f32 " \
        "{%0,%1,%2,%3}, {%4,%5,%6,%7}, {%8,%9}, {%0,%1,%2,%3};" \
        : "+f"((d)[0]), "+f"((d)[1]), "+f"((d)[2]), "+f"((d)[3]) \
        : "r"((a)[0]), "r"((a)[1]), "r"((a)[2]), "r"((a)[3]), "r"(b0), "r"(b1))

// element-type helpers
__device__ __forceinline__ float et2f(__nv_bfloat16 v) { return __bfloat162float(v); }
__device__ __forceinline__ float et2f(__half v)        { return __half2float(v); }
__device__ __forceinline__ void  f2et(float x, __nv_bfloat16& h) { h = __float2bfloat16(x); }
__device__ __forceinline__ void  f2et(float x, __half& h)        { h = __float2half(x); }
__device__ __forceinline__ void  st2(__nv_bfloat16* p, __nv_bfloat16 a, __nv_bfloat16 b) {
    *reinterpret_cast<__nv_bfloat162*>(p) = __halves2bfloat162(a, b);
}
__device__ __forceinline__ void  st2(__half* p, __half a, __half b) {
    *reinterpret_cast<__half2*>(p) = __halves2half2(a, b);
}
__device__ __forceinline__ float2 ld2f(const __nv_bfloat16* p) {
    return __bfloat1622float2(*reinterpret_cast<const __nv_bfloat162*>(p));
}
__device__ __forceinline__ float2 ld2f(const __half* p) {
    return __half22float2(*reinterpret_cast<const __half2*>(p));
}

// ============================================================================
// Unified split tensor GEMM.
//   ET = bf16 (ISH=0) or fp16 (ISH=1).
//   NPROD=3: products hh + lh + hl (A hi/lo, B hi/lo).
//   NPROD=2: products hh + lh (A hi/lo, B single).
//   V = alpha * A @ B^T [+ rbeta*(hi+lo of Cin) if BETAHL] [+ I if ADDI]
//   FPOUT: fp32 to C.  HLOUT: ET hi/lo to Chl.  F16S: fp16 single to Chl.
// ============================================================================
#define TILE_B   8192
#define GEMM_THR 128

template <int ISH, int NPROD, int ADDI, int TRI, int BETAHL, int ZB,
          int FPOUT, int HLOUT, int F16S>
__global__ void __launch_bounds__(GEMM_THR, 2)
u_gemm(const void* __restrict__ A_, const void* __restrict__ B_,
       float* __restrict__ C, void* __restrict__ Chl,
       const void* __restrict__ Cin_,
       int K, int lda2, int loA, int ldb2, int loB,
       int ldc, int ldchl, float alpha, float rbeta,
       long long zAs, long long zBs, long long zCHs, int M0, int dM)
{
    using ET = typename std::conditional<ISH, __half, __nv_bfloat16>::type;
    const ET* A = (const ET*)A_;
    const ET* B = (const ET*)B_;
    const ET* Cin = (const ET*)Cin_;
    constexpr int NT = NPROD + 1;                 // tiles per stage
    constexpr int STAGE = NT * TILE_B;

    extern __shared__ __align__(128) char smem[];
    const uint32_t s0 = smem_u32(smem);
    const int tid  = threadIdx.x;
    const int lane = tid & 31;
    const int wid  = tid >> 5;
    const int wm   = wid >> 1;
    const int wn   = wid & 1;

    if (ZB) {
        const int z = blockIdx.z;
        A += zAs * z; B += zBs * z;
        if (HLOUT || F16S) Chl = (void*)((char*)Chl + zCHs * 2 * (long long)z);
        if ((int)(blockIdx.y * 128) >= M0 - dM * z) return;
    }

    int row0, col0;
    if (TRI) {
        int bid = blockIdx.x;
        int r = 0;
        while ((r + 1) * (r + 2) / 2 <= bid) ++r;
        row0 = r * 128;
        col0 = (bid - r * (r + 1) / 2) * 128;
    } else {
        row0 = blockIdx.y * 128;
        col0 = blockIdx.x * 128;
    }

    const int T = K / 32;

    float acc[4][8][4];
#pragma unroll
    for (int i = 0; i < 4; i++)
#pragma unroll
        for (int j = 0; j < 8; j++)
#pragma unroll
            for (int q = 0; q < 4; q++) acc[i][j][q] = 0.f;

    auto load_stage = [&](int s) {
        const int k0 = s * 32;
        const uint32_t base = s0 + (s % 3) * STAGE;
#pragma unroll
        for (int qq = 0; qq < 4; ++qq) {
            const int jj = tid + qq * GEMM_THR;
            const int r  = jj >> 2;
            const int cc = jj & 3;
            const uint32_t soff = r * 64 + ((cc ^ ((r >> 1) & 3)) << 4);
            const ET* ag = A + (size_t)(row0 + r) * lda2 + k0 + cc * 8;
            const ET* bg = B + (size_t)(col0 + r) * ldb2 + k0 + cc * 8;
            cpa16(base + 0 * TILE_B + soff, ag);
            cpa16(base + 1 * TILE_B + soff, ag + loA);
            cpa16(base + 2 * TILE_B + soff, bg);
            if (NPROD == 3)
                cpa16(base + 3 * TILE_B + soff, bg + loB);
        }
        CPA_COMMIT();
    };

    load_stage(0); load_stage(1);

    for (int s = 0; s < T; ++s) {
        CPA_WAIT(1);
        __syncthreads();
        if (s + 2 < T) load_stage(s + 2);

        const uint32_t buf = s0 + (s % 3) * STAGE;
#pragma unroll
        for (int kk = 0; kk < 2; ++kk) {
            uint32_t ah[4][4], al[4][4], bb[8][2];
#pragma unroll
            for (int mi = 0; mi < 4; ++mi) {
                const int row = wm * 64 + mi * 16 + ((lane >> 3) & 1) * 8 + (lane & 7);
                const int cc  = kk * 2 + (lane >> 4);
                const uint32_t off = row * 64 + ((cc ^ ((row >> 1) & 3)) << 4);
                LDSM4(ah[mi][0], ah[mi][1], ah[mi][2], ah[mi][3], buf + 0 * TILE_B + off);
                LDSM4(al[mi][0], al[mi][1], al[mi][2], al[mi][3], buf + 1 * TILE_B + off);
            }
#pragma unroll
            for (int p = 0; p < 4; ++p) {
                const int row = wn * 64 + p * 16 + (lane >> 4) * 8 + (lane & 7);
                const int cc  = kk * 2 + ((lane >> 3) & 1);
                const uint32_t off = row * 64 + ((cc ^ ((row >> 1) & 3)) << 4);
                LDSM4(bb[p * 2][0], bb[p * 2][1], bb[p * 2 + 1][0], bb[p * 2 + 1][1],
                      buf + 2 * TILE_B + off);
            }
#pragma unroll
            for (int mi = 0; mi < 4; ++mi)
#pragma unroll
                for (int nj = 0; nj < 8; ++nj) {
                    if (ISH) {
                        MMA_FP(acc[mi][nj], ah[mi], bb[nj][0], bb[nj][1]);  // hh
                        MMA_FP(acc[mi][nj], al[mi], bb[nj][0], bb[nj][1]);  // lh
                    } else {
                        MMA_BF(acc[mi][nj], ah[mi], bb[nj][0], bb[nj][1]);
                        MMA_BF(acc[mi][nj], al[mi], bb[nj][0], bb[nj][1]);
                    }
                }
            if (NPROD == 3) {
#pragma unroll
                for (int p = 0; p < 4; ++p) {
                    const int row = wn * 64 + p * 16 + (lane >> 4) * 8 + (lane & 7);
                    const int cc  = kk * 2 + ((lane >> 3) & 1);
                    const uint32_t off = row * 64 + ((cc ^ ((row >> 1) & 3)) << 4);
                    LDSM4(bb[p * 2][0], bb[p * 2][1], bb[p * 2 + 1][0], bb[p * 2 + 1][1],
                          buf + 3 * TILE_B + off);
                }
#pragma unroll
                for (int mi = 0; mi < 4; ++mi)
#pragma unroll
                    for (int nj = 0; nj < 8; ++nj) {
                        if (ISH) { MMA_FP(acc[mi][nj], ah[mi], bb[nj][0], bb[nj][1]); }
                        else     { MMA_BF(acc[mi][nj], ah[mi], bb[nj][0], bb[nj][1]); }
                    }
            }
        }
    }

    const int g = lane >> 2, t = lane & 3;
    const int hlf = ldchl >> 1;
#pragma unroll
    for (int mi = 0; mi < 4; ++mi) {
#pragma unroll
        for (int nj = 0; nj < 8; ++nj) {
            const int r_ = row0 + wm * 64 + mi * 16 + g;
            const int c_ = col0 + wn * 64 + nj * 8 + 2 * t;
            float2 v, v2;
            v.x  = alpha * acc[mi][nj][0];
            v.y  = alpha * acc[mi][nj][1];
            v2.x = alpha * acc[mi][nj][2];
            v2.y = alpha * acc[mi][nj][3];
            if (BETAHL) {
                float2 ih  = ld2f(&Cin[(size_t)r_ * ldchl + c_]);
                float2 il  = ld2f(&Cin[(size_t)r_ * ldchl + hlf + c_]);
                float2 ih2 = ld2f(&Cin[(size_t)(r_ + 8) * ldchl + c_]);
                float2 il2 = ld2f(&Cin[(size_t)(r_ + 8) * ldchl + hlf + c_]);
                v.x  += rbeta * (ih.x  + il.x);
                v.y  += rbeta * (ih.y  + il.y);
                v2.x += rbeta * (ih2.x + il2.x);
                v2.y += rbeta * (ih2.y + il2.y);
            }
            if (ADDI) {
                if (r_ == c_)     v.x  += 1.f;
                if (r_ == c_ + 1) v.y  += 1.f;
                if (r_ + 8 == c_)     v2.x += 1.f;
                if (r_ + 8 == c_ + 1) v2.y += 1.f;
            }
            if (FPOUT) {
                *reinterpret_cast<float2*>(&C[(size_t)r_ * ldc + c_])       = v;
                *reinterpret_cast<float2*>(&C[(size_t)(r_ + 8) * ldc + c_]) = v2;
            }
            if (HLOUT) {
                ET* Cb = (ET*)Chl;
                ET hx, hy, hx2, hy2;
                f2et(v.x,  hx);  f2et(v.y,  hy);
                f2et(v2.x, hx2); f2et(v2.y, hy2);
                ET lx, ly, lx2, ly2;
                f2et(v.x  - et2f(hx),  lx);  f2et(v.y  - et2f(hy),  ly);
                f2et(v2.x - et2f(hx2), lx2); f2et(v2.y - et2f(hy2), ly2);
                st2(&Cb[(size_t)r_ * ldchl + c_],              hx,  hy);
                st2(&Cb[(size_t)r_ * ldchl + hlf + c_],        lx,  ly);
                st2(&Cb[(size_t)(r_ + 8) * ldchl + c_],        hx2, hy2);
                st2(&Cb[(size_t)(r_ + 8) * ldchl + hlf + c_],  lx2, ly2);
            }
            if (F16S) {
                __half* Ch = (__half*)Chl;
                *reinterpret_cast<__half2*>(&Ch[(size_t)r_ * ldchl + c_]) =
                    __floats2half2_rn(v.x, v.y);
                *reinterpret_cast<__half2*>(&Ch[(size_t)(r_ + 8) * ldchl + c_]) =
                    __floats2half2_rn(v2.x, v2.y);
            }
        }
    }
}

// ============================================================================
// fp16 single-product GEMM (out = P @ X): K=64 per stage, 128B-row swizzle.
// ============================================================================
#define TILE_H   16384
#define STAGE_H  (2 * TILE_H)
#define GEMMH_SMEM (3 * STAGE_H)

__global__ void __launch_bounds__(GEMM_THR, 2)
mma_gemm_h(const __half* __restrict__ A, const __half* __restrict__ B,
           float* __restrict__ C, int K, int lda, int ldb, int ldc)
{
    extern __shared__ __align__(128) char smem[];
    const uint32_t s0 = smem_u32(smem);
    const int tid  = threadIdx.x;
    const int lane = tid & 31;
    const int wid  = tid >> 5;
    const int wm   = wid >> 1;
    const int wn   = wid & 1;
    const int row0 = blockIdx.y * 128;
    const int col0 = blockIdx.x * 128;
    const int T = K / 64;

    float acc[4][8][4];
#pragma unroll
    for (int i = 0; i < 4; i++)
#pragma unroll
        for (int j = 0; j < 8; j++)
#pragma unroll
            for (int q = 0; q < 4; q++) acc[i][j][q] = 0.f;

    auto load_stage = [&](int s) {
        const int k0 = s * 64;
        const uint32_t base = s0 + (s % 3) * STAGE_H;
#pragma unroll
        for (int qq = 0; qq < 8; ++qq) {
            const int jj = tid + qq * GEMM_THR;
            const int r  = jj >> 3;
            const int cc = jj & 7;
            const uint32_t soff = r * 128 + ((cc ^ (r & 7)) << 4);
            cpa16(base + soff,          A + (size_t)(row0 + r) * lda + k0 + cc * 8);
            cpa16(base + TILE_H + soff, B + (size_t)(col0 + r) * ldb + k0 + cc * 8);
        }
        CPA_COMMIT();
    };

    load_stage(0); load_stage(1);

    for (int s = 0; s < T; ++s) {
        CPA_WAIT(1);
        __syncthreads();
        if (s + 2 < T) load_stage(s + 2);

        const uint32_t buf = s0 + (s % 3) * STAGE_H;
#pragma unroll
        for (int kk = 0; kk < 4; ++kk) {
            uint32_t ah[4][4], bb[8][2];
#pragma unroll
            for (int mi = 0; mi < 4; ++mi) {
                const int row = wm * 64 + mi * 16 + ((lane >> 3) & 1) * 8 + (lane & 7);
                const int cc  = kk * 2 + (lane >> 4);
                const uint32_t off = row * 128 + ((cc ^ (row & 7)) << 4);
                LDSM4(ah[mi][0], ah[mi][1], ah[mi][2], ah[mi][3], buf + off);
            }
#pragma unroll
            for (int p = 0; p < 4; ++p) {
                const int row = wn * 64 + p * 16 + (lane >> 4) * 8 + (lane & 7);
                const int cc  = kk * 2 + ((lane >> 3) & 1);
                const uint32_t off = row * 128 + ((cc ^ (row & 7)) << 4);
                LDSM4(bb[p * 2][0], bb[p * 2][1], bb[p * 2 + 1][0], bb[p * 2 + 1][1],
                      buf + TILE_H + off);
            }
#pragma unroll
            for (int mi = 0; mi < 4; ++mi)
#pragma unroll
                for (int nj = 0; nj < 8; ++nj)
                    MMA_FP(acc[mi][nj], ah[mi], bb[nj][0], bb[nj][1]);
        }
    }

    const int g = lane >> 2, t = lane & 3;
#pragma unroll
    for (int mi = 0; mi < 4; ++mi) {
#pragma unroll
        for (int nj = 0; nj < 8; ++nj) {
            const int r_ = row0 + wm * 64 + mi * 16 + g;
            const int c_ = col0 + wn * 64 + nj * 8 + 2 * t;
            *reinterpret_cast<float2*>(&C[(size_t)r_ * ldc + c_]) =
                make_float2(acc[mi][nj][0], acc[mi][nj][1]);
            *reinterpret_cast<float2*>(&C[(size_t)(r_ + 8) * ldc + c_]) =
                make_float2(acc[mi][nj][2], acc[mi][nj][3]);
        }
    }
}

// ============================================================================
// Row-normalize U -> Vn (fp32) + Vn_hl (bf16 hi/lo)
// ============================================================================
__global__ void normalize_kernel(const float* __restrict__ U) {
    int row = blockIdx.x;
    const float* u = U + (size_t)row * D_DIM;
    __shared__ float red[256];
    float s = 0.f;
    for (int c = threadIdx.x; c < D_DIM; c += 256) { float v = u[c]; s += v * v; }
    red[threadIdx.x] = s;
    __syncthreads();
    for (int off = 128; off > 0; off >>= 1) {
        if (threadIdx.x < off) red[threadIdx.x] += red[threadIdx.x + off];
        __syncthreads();
    }
    float inv = rsqrtf(red[0]);
    for (int c = threadIdx.x; c < D_DIM; c += 256) {
        float v = u[c] * inv;
        g_Vn[(size_t)row * D_DIM + c] = v;
        __nv_bfloat16 h = __float2bfloat16(v);
        g_Vn_hl[(size_t)row * 2 * D_DIM + c]         = h;
        g_Vn_hl[(size_t)row * 2 * D_DIM + D_DIM + c] =
            __float2bfloat16(v - __bfloat162float(h));
    }
}

// ============================================================================
// conversions
// ============================================================================
__global__ void conv_hl_T_gen(const float* __restrict__ in, int R, int C,
                              __nv_bfloat16* __restrict__ out, int outld,
                              int outcol0, int looff,
                              long long zIn, long long zOut) {
    in  += zIn  * blockIdx.z;
    out += zOut * blockIdx.z;
    __shared__ float t[32][33];
    int r0 = blockIdx.y * 32, c0 = blockIdx.x * 32;
    int tx = threadIdx.x, ty = threadIdx.y;
    for (int i = 0; i < 32; i += 8)
        t[ty + i][tx] = in[(size_t)(r0 + ty + i) * C + c0 + tx];
    __syncthreads();
    for (int i = 0; i < 32; i += 8) {
        float x = t[tx][ty + i];
        __nv_bfloat16 h = __float2bfloat16(x);
        out[(size_t)(c0 + ty + i) * outld + outcol0 + r0 + tx] = h;
        out[(size_t)(c0 + ty + i) * outld + looff + outcol0 + r0 + tx] =
            __float2bfloat16(x - __bfloat162float(h));
    }
}
// Vn transpose: emits fp16 hi|lo (VnT_h2)
__global__ void conv_T_vn(const float* __restrict__ in) {
    __shared__ float t[32][33];
    int r0 = blockIdx.y * 32, c0 = blockIdx.x * 32;
    int tx = threadIdx.x, ty = threadIdx.y;
    for (int i = 0; i < 32; i += 8)
        t[ty + i][tx] = in[(size_t)(r0 + ty + i) * D_DIM + c0 + tx];
    __syncthreads();
    for (int i = 0; i < 32; i += 8) {
        float x = t[tx][ty + i];
        __half h = __float2half(x);
        size_t ro = (size_t)(c0 + ty + i);
        g_VnT_h2[ro * 2 * D_DIM + r0 + tx]         = h;
        g_VnT_h2[ro * 2 * D_DIM + D_DIM + r0 + tx] =
            __float2half(x - __half2float(h));
    }
}
__global__ void conv_h_T(const float* __restrict__ in, int R, int C,
                         __half* __restrict__ out, int outld) {
    __shared__ float t[32][33];
    int r0 = blockIdx.y * 32, c0 = blockIdx.x * 32;
    int tx = threadIdx.x, ty = threadIdx.y;
    for (int i = 0; i < 32; i += 8)
        t[ty + i][tx] = in[(size_t)(r0 + ty + i) * C + c0 + tx];
    __syncthreads();
    for (int i = 0; i < 32; i += 8)
        out[(size_t)(c0 + ty + i) * outld + r0 + tx] = __float2half(t[tx][ty + i]);
}
// Seed RHST_h2 block 0 = 2 * VnT block 0
__global__ void seed_rhst0() {
    int r = blockIdx.x;
    int c = threadIdx.x;
    size_t base = (size_t)r * 2 * D_DIM;
    float x = 2.f * (__half2float(g_VnT_h2[base + c]) +
                     __half2float(g_VnT_h2[base + D_DIM + c]));
    __half h = __float2half(x);
    g_RHST_h2[base + c]         = h;
    g_RHST_h2[base + D_DIM + c] = __float2half(x - __half2float(h));
}

// ============================================================================
// Diag-block inversion, column-sliced (NBLK, 8) + 8-column band rounds.
// ============================================================================
#define INV_SMEM ((128 * 129 + 128 * 17) * (int)sizeof(float))
__global__ void invert_diag_kernel() {
    extern __shared__ float sm[];
    float (*Gs)[129] = (float (*)[129])sm;
    float (*Zs)[17]  = (float (*)[17])(sm + 128 * 129);
    const int b0 = blockIdx.x * NB;
    const int c0 = blockIdx.y * 16;
    const int tid = threadIdx.x;

    for (int idx = tid; idx < 128 * 128; idx += 256) {
        int r = idx >> 7, c = idx & 127;
        Gs[r][c] = g_G[(size_t)(b0 + r) * D_DIM + b0 + c];
    }
    for (int idx = tid; idx < 128 * 16; idx += 256) {
        int r = idx >> 4, c = idx & 15;
        Zs[r][c] = (r == c0 + c) ? 1.f : 0.f;
    }
    __syncthreads();

    for (int j = 0; j < NB; j += 8) {
        if (tid < 32) {
            const int c  = tid & 15;
            const int rg = tid >> 4;
#pragma unroll
            for (int q = 0; q < 7; ++q) {
                float zq = Zs[j + q][c];
#pragma unroll
                for (int rr = 0; rr < 4; ++rr) {
                    int r = rg * 4 + rr;
                    if (r > q)
                        Zs[j + r][c] -= 2.f * Gs[j + r][j + q] * zq;
                }
                __syncwarp();
            }
        }
        __syncthreads();
        const int rows = NB - 8 - j;
        for (int idx = tid; idx < rows * 16; idx += 256) {
            const int r = j + 8 + (idx >> 4);
            const int c = idx & 15;
            float acc = Zs[r][c];
#pragma unroll
            for (int q = 0; q < 8; ++q)
                acc -= 2.f * Gs[r][j + q] * Zs[j + q][c];
            Zs[r][c] = acc;
        }
        __syncthreads();
    }

    float* outp = g_Tinv + (size_t)blockIdx.x * NB * NB;
    for (int idx = tid; idx < 128 * 16; idx += 256) {
        int r = idx >> 4, c = idx & 15;
        outp[(size_t)r * NB + c0 + c] = Zs[r][c];
    }
}

// ============================================================================
// Pair-combine: 7 Tinv2 blocks (256x256) fp32 + fused fp16 hi/lo split.
// ============================================================================
#define CMB_SMEM (3 * 128 * 129 * (int)sizeof(float))
__device__ __forceinline__ void cmb_wr_h2(__half* Thl, int r, int c, float x) {
    __half h = __float2half(x);
    Thl[(size_t)r * 512 + c]       = h;
    Thl[(size_t)r * 512 + 256 + c] = __float2half(x - __half2float(h));
}
__global__ void __launch_bounds__(256, 1) combine_tinv() {
    extern __shared__ float sm[];
    float (*Abuf)[129] = (float (*)[129])sm;
    float (*Bbuf)[129] = (float (*)[129])(sm + 128 * 129);
    float (*Tm)[129]   = (float (*)[129])(sm + 2 * 128 * 129);
    const int p = blockIdx.x;
    const int tid = threadIdx.x;
    const int trow = (tid / 16) * 8;
    const int tcol = (tid % 16) * 8;
    const float* InvA = g_Tinv + (size_t)(2 * p)     * NB * NB;
    const float* InvB = g_Tinv + (size_t)(2 * p + 1) * NB * NB;
    const size_t g21 = (size_t)(p * 256 + 128) * D_DIM + p * 256;
    __half* Thl = g_Tinv2_h2 + (size_t)p * NB2 * 2 * NB2;

    for (int idx = tid; idx < 128 * 128; idx += 256) {
        int r = idx >> 7, c = idx & 127;
        Abuf[r][c] = 2.f * g_G[g21 + (size_t)r * D_DIM + c];
        Bbuf[r][c] = InvA[idx];
    }
    __syncthreads();
    {
        float acc[8][8];
#pragma unroll
        for (int i = 0; i < 8; i++)
#pragma unroll
            for (int j = 0; j < 8; j++) acc[i][j] = 0.f;
        for (int k = 0; k < 128; ++k) {
            float a[8], b[8];
#pragma unroll
            for (int i = 0; i < 8; i++) a[i] = Abuf[trow + i][k];
#pragma unroll
            for (int j = 0; j < 8; j++) b[j] = Bbuf[k][tcol + j];
#pragma unroll
            for (int i = 0; i < 8; i++)
#pragma unroll
                for (int j = 0; j < 8; j++) acc[i][j] += a[i] * b[j];
        }
        __syncthreads();
#pragma unroll
        for (int i = 0; i < 8; i++)
#pragma unroll
            for (int j = 0; j < 8; j++) Tm[trow + i][tcol + j] = acc[i][j];
    }
    __syncthreads();
    for (int idx = tid; idx < 128 * 128; idx += 256) {
        int r = idx >> 7, c = idx & 127;
        Abuf[r][c] = InvB[idx];
    }
    __syncthreads();
    float* outp = g_Tinv2 + (size_t)p * NB2 * NB2;
    {
        float acc[8][8];
#pragma unroll
        for (int i = 0; i < 8; i++)
#pragma unroll
            for (int j = 0; j < 8; j++) acc[i][j] = 0.f;
        for (int k = 0; k < 128; ++k) {
            float a[8], b[8];
#pragma unroll
            for (int i = 0; i < 8; i++) a[i] = Abuf[trow + i][k];
#pragma unroll
            for (int j = 0; j < 8; j++) b[j] = Tm[k][tcol + j];
#pragma unroll
            for (int i = 0; i < 8; i++)
#pragma unroll
                for (int j = 0; j < 8; j++) acc[i][j] += a[i] * b[j];
        }
#pragma unroll
        for (int i = 0; i < 8; i++) {
#pragma unroll
            for (int j = 0; j < 8; j++) {
                int r = trow + i, c = tcol + j;
                float q21 = -acc[i][j];
                outp[(size_t)(128 + r) * NB2 + c] = q21;
                cmb_wr_h2(Thl, 128 + r, c, q21);
            }
        }
    }
    for (int idx = tid; idx < 128 * 128; idx += 256) {
        int r = idx >> 7, c = idx & 127;
        float q11 = Bbuf[r][c];
        float q22 = Abuf[r][c];
        outp[(size_t)r * NB2 + c]               = q11;
        outp[(size_t)r * NB2 + 128 + c]         = 0.f;
        outp[(size_t)(128 + r) * NB2 + 128 + c] = q22;
        cmb_wr_h2(Thl, r, c, q11);
        cmb_wr_h2(Thl, r, 128 + c, 0.f);
        cmb_wr_h2(Thl, 128 + r, 128 + c, q22);
    }
}

// ============================================================================
extern "C" void kernel_launch(void* const* d_in, const int* in_sizes, int n_in,
                              void* d_out, int out_size)
{
    const float* X;
    const float* U;
    if (in_sizes[0] == D_DIM * D_DIM && in_sizes[1] != D_DIM * D_DIM) {
        U = (const float*)d_in[0]; X = (const float*)d_in[1];
    } else {
        X = (const float*)d_in[0]; U = (const float*)d_in[1];
    }
    float* out = (float*)d_out;

    float *Vn, *G, *Tinv2;
    cudaGetSymbolAddress((void**)&Vn,    g_Vn);
    cudaGetSymbolAddress((void**)&G,     g_G);
    cudaGetSymbolAddress((void**)&Tinv2, g_Tinv2);
    __nv_bfloat16 *Vn_hl, *G_hl, *Tinv2T_hl;
    __half *VnT_h2, *RHST_h2, *WtT_h2, *Tinv2_h2, *S_h, *P_h, *XT_h;
    cudaGetSymbolAddress((void**)&Vn_hl,     g_Vn_hl);
    cudaGetSymbolAddress((void**)&G_hl,      g_G_hl);
    cudaGetSymbolAddress((void**)&Tinv2T_hl, g_Tinv2T_hl);
    cudaGetSymbolAddress((void**)&VnT_h2,    g_VnT_h2);
    cudaGetSymbolAddress((void**)&RHST_h2,   g_RHST_h2);
    cudaGetSymbolAddress((void**)&WtT_h2,    g_WtT_h2);
    cudaGetSymbolAddress((void**)&Tinv2_h2,  g_Tinv2_h2);
    cudaGetSymbolAddress((void**)&S_h,       g_S_h);
    cudaGetSymbolAddress((void**)&P_h,       g_P_h);
    cudaGetSymbolAddress((void**)&XT_h,      g_XT_h);

    const int SM3 = 3 * 4 * TILE_B;   // 98304 (NPROD=3)
    const int SM2 = 3 * 3 * TILE_B;   // 73728 (NPROD=2)

    // G GEMM (bf16, 3-prod, TRI, fp32+hl out)
    auto kG  = u_gemm<0,3,0,1,0,0,1,1,0>;
    // S GEMM (bf16, 3-prod, ZB, fp16 single out)
    auto kS  = u_gemm<0,3,0,0,0,1,0,0,1>;
    // chain (fp16, 2-prod, BETAHL, fp16 hl out)
    auto kCh = u_gemm<1,2,0,0,1,0,0,1,0>;
    // WtT (fp16, 3-prod, ZB, fp16 hl out)
    auto kW  = u_gemm<1,3,0,0,0,1,0,1,0>;
    // P (fp16, 2-prod, ADDI, fp16 single out)
    auto kP  = u_gemm<1,2,1,0,0,0,0,0,1>;

    cudaFuncSetAttribute(invert_diag_kernel,
                         cudaFuncAttributeMaxDynamicSharedMemorySize, INV_SMEM);
    cudaFuncSetAttribute(combine_tinv,
                         cudaFuncAttributeMaxDynamicSharedMemorySize, CMB_SMEM);
    cudaFuncSetAttribute(kG,  cudaFuncAttributeMaxDynamicSharedMemorySize, SM3);
    cudaFuncSetAttribute(kS,  cudaFuncAttributeMaxDynamicSharedMemorySize, SM3);
    cudaFuncSetAttribute(kCh, cudaFuncAttributeMaxDynamicSharedMemorySize, SM2);
    cudaFuncSetAttribute(kW,  cudaFuncAttributeMaxDynamicSharedMemorySize, SM3);
    cudaFuncSetAttribute(kP,  cudaFuncAttributeMaxDynamicSharedMemorySize, SM2);
    cudaFuncSetAttribute(mma_gemm_h,
                         cudaFuncAttributeMaxDynamicSharedMemorySize, GEMMH_SMEM);

    const dim3 t32x8(32, 8);
    const int D2 = 2 * D_DIM;   // 3584

    // 0) Vn (+bf16 hl fused)
    normalize_kernel<<<D_DIM, 256>>>(U);
    // 1) VnT fp16 hi/lo
    conv_T_vn<<<dim3(D_DIM / 32, D_DIM / 32), t32x8>>>(Vn);
    // 2) G = Vn @ Vn^T (lower tiles; fp32 + bf16 hl fused)
    kG<<<NBLK * (NBLK + 1) / 2, GEMM_THR, SM3>>>(
        Vn_hl, Vn_hl, G, G_hl, nullptr,
        D_DIM, D2, D_DIM, D2, D_DIM, D_DIM, D2, 1.f, 0.f, 0, 0, 0, D_DIM, 0);
    // 3) invert 14 diag blocks
    invert_diag_kernel<<<dim3(NBLK, 8), 256, INV_SMEM>>>();
    // 4) combine into 7 Tinv2 blocks (fp32 + fp16 hl fused)
    combine_tinv<<<NBLK2, 256, CMB_SMEM>>>();
    // 4b) Tinv2T bf16 hi/lo (for S GEMM B)
    conv_hl_T_gen<<<dim3(NB2 / 32, NB2 / 32, NBLK2), t32x8>>>(
        Tinv2, NB2, NB2, Tinv2T_hl, 2 * NB2, 0, NB2,
        (long long)NB2 * NB2, (long long)NB2 * 2 * NB2);
    // 5) S_i = 2 * G[(i+1)*256:, blk i] @ Tinv2_i^T  (fp16 single out)
    kS<<<dim3(NB2 / 128, MREM0 / 128, NBLK2 - 1), GEMM_THR, SM3>>>(
        G_hl + (size_t)NB2 * D2, Tinv2T_hl, nullptr, S_h, nullptr,
        NB2, D2, D_DIM, 2 * NB2, NB2, 0, NB2, 2.f, 0.f,
        (long long)NB2 * D2 + NB2,
        (long long)NB2 * 2 * NB2,
        (long long)MREM0 * NB2,
        MREM0, NB2);
    // 5b) seed RHST_h2 block 0
    seed_rhst0<<<D_DIM, 256>>>();

    // 6) transposed chain (fp16 2-product)
    for (int i = 0; i < NBLK2 - 1; ++i) {
        int mrem = D_DIM - (i + 1) * NB2;
        const __half* Cin = (i == 0) ? (VnT_h2 + NB2) : (RHST_h2 + (i + 1) * NB2);
        float rbeta = (i == 0) ? 2.f : 1.f;
        kCh<<<dim3(mrem / 128, D_DIM / 128), GEMM_THR, SM2>>>(
            RHST_h2 + (size_t)i * NB2,
            S_h + (size_t)i * MREM0 * NB2,
            nullptr, RHST_h2 + (i + 1) * NB2, Cin,
            NB2, D2, D_DIM, NB2, 0, 0, D2, -1.f, rbeta,
            0, 0, 0, D_DIM, 0);
    }

    // 7) WtT(:, bi) = RHST(:, bi) @ Tinv2_bi^T  (fp16 3-prod, z-batched)
    kW<<<dim3(NB2 / 128, D_DIM / 128, NBLK2), GEMM_THR, SM3>>>(
        RHST_h2, Tinv2_h2, nullptr, WtT_h2, nullptr,
        NB2, D2, D_DIM, 2 * NB2, NB2, 0, D2, 1.f, 0.f,
        (long long)NB2,
        (long long)NB2 * 2 * NB2,
        (long long)NB2,
        D_DIM, 0);

    // 8) P = I - WtT @ VnT-hi  (fp16 2-prod, fp16 single out)
    kP<<<dim3(D_DIM / 128, D_DIM / 128), GEMM_THR, SM2>>>(
        WtT_h2, VnT_h2, nullptr, P_h, nullptr,
        D_DIM, D2, D_DIM, D2, 0, 0, D_DIM, -1.f, 0.f, 0, 0, 0, D_DIM, 0);

    // 9) X^T fp16
    conv_h_T<<<dim3(B_DIM / 32, D_DIM / 32), t32x8>>>(X, D_DIM, B_DIM, XT_h, D_DIM);

    // 10) out = P @ X
    mma_gemm_h<<<dim3(B_DIM / 128, D_DIM / 128), GEMM_THR, GEMMH_SMEM>>>(
        P_h, XT_h, out, D_DIM, D_DIM, D_DIM, B_DIM);

    (void)n_in; (void)out_size;
}

// round 17
// speedup vs baseline: 1.4378x; 1.4378x over previous
#include <cuda_runtime.h>
#include <cuda_bf16.h>
#include <cuda_fp16.h>
#include <cstdint>

#define D_DIM 1792
#define B_DIM 8192
#define NB 128
#define NBLK (D_DIM / NB)     // 14
#define NB2 256
#define NBLK2 (D_DIM / NB2)   // 7
#define MREM0 1536

// ---------------- fp32 scratch ----------------
__device__ __align__(16) float g_Vn   [ (size_t)D_DIM * D_DIM ];
__device__ __align__(16) float g_G    [ (size_t)D_DIM * D_DIM ];
__device__ __align__(16) float g_Tinv [ (size_t)NBLK * NB * NB ];
__device__ __align__(16) float g_Tinv2[ (size_t)NBLK2 * NB2 * NB2 ];

// ---------------- bf16 hi|lo scratch ----------------
__device__ __align__(16) __nv_bfloat16 g_Vn_hl    [ (size_t)D_DIM * 2 * D_DIM ];
__device__ __align__(16) __nv_bfloat16 g_VnT_hl   [ (size_t)D_DIM * 2 * D_DIM ];
__device__ __align__(16) __nv_bfloat16 g_G_hl     [ (size_t)D_DIM * 2 * D_DIM ];
__device__ __align__(16) __nv_bfloat16 g_RHST_hl  [ (size_t)D_DIM * 2 * D_DIM ];
__device__ __align__(16) __nv_bfloat16 g_Tinv2_hl [ (size_t)NBLK2 * NB2 * 2 * NB2 ];
__device__ __align__(16) __nv_bfloat16 g_Tinv2T_hl[ (size_t)NBLK2 * NB2 * 2 * NB2 ];
__device__ __align__(16) __nv_bfloat16 g_S_hl     [ (size_t)(NBLK2 - 1) * MREM0 * 2 * NB2 ];

// ---------------- fp16 operands ----------------
__device__ __align__(16) __half g_P_h    [ (size_t)D_DIM * D_DIM ];
__device__ __align__(16) __half g_XT_h   [ (size_t)B_DIM * D_DIM ];
__device__ __align__(16) __half g_WtT_h2 [ (size_t)D_DIM * 2 * D_DIM ];  // hi|lo fp16
__device__ __align__(16) __half g_VnT_h  [ (size_t)D_DIM * D_DIM ];

// ============================================================================
// helpers
// ============================================================================
__device__ __forceinline__ uint32_t smem_u32(const void* p) {
    uint32_t a;
    asm("{ .reg .u64 t; cvta.to.shared.u64 t, %1; cvt.u32.u64 %0, t; }"
        : "=r"(a) : "l"(p));
    return a;
}
__device__ __forceinline__ void cpa16(uint32_t s, const void* g) {
    asm volatile("cp.async.cg.shared.global [%0], [%1], 16;" :: "r"(s), "l"(g));
}
#define CPA_COMMIT() asm volatile("cp.async.commit_group;" ::: "memory")
#define CPA_WAIT(n)  asm volatile("cp.async.wait_group %0;" :: "n"(n) : "memory")

#define LDSM4(r0, r1, r2, r3, addr) \
    asm volatile("ldmatrix.sync.aligned.m8n8.x4.shared.b16 {%0,%1,%2,%3}, [%4];" \
        : "=r"(r0), "=r"(r1), "=r"(r2), "=r"(r3) : "r"(addr))

#define MMA16816(d, a, b0, b1) \
    asm volatile("mma.sync.aligned.m16n8k16.row.col.f32.bf16.bf16.f32 " \
        "{%0,%1,%2,%3}, {%4,%5,%6,%7}, {%8,%9}, {%0,%1,%2,%3};" \
        : "+f"((d)[0]), "+f"((d)[1]), "+f"((d)[2]), "+f"((d)[3]) \
        : "r"((a)[0]), "r"((a)[1]), "r"((a)[2]), "r"((a)[3]), "r"(b0), "r"(b1))

#define MMA16816H(d, a, b0, b1) \
    asm volatile("mma.sync.aligned.m16n8k16.row.col.f32.f16.f16.f32 " \
        "{%0,%1,%2,%3}, {%4,%5,%6,%7}, {%8,%9}, {%0,%1,%2,%3};" \
        : "+f"((d)[0]), "+f"((d)[1]), "+f"((d)[2]), "+f"((d)[3]) \
        : "r"((a)[0]), "r"((a)[1]), "r"((a)[2]), "r"((a)[3]), "r"(b0), "r"(b1))

// ============================================================================
// Generalized bf16-split tensor GEMM (3 products hh+lh+hl):
//   V = alpha * A @ B^T  [+ rbeta*(hi+lo of Cin) if BETAHL]  [+ I if ADDI]
//   FPOUT: fp32 out.  HLOUT: bf16 hi/lo out.  F16M: 1 = fp16 single out,
//   2 = fp16 hi/lo out (half offset = ldchl/2).
// ============================================================================
#define TILE_B   8192
#define STAGE_B  (4 * TILE_B)
#define GEMM_SMEM (3 * STAGE_B)
#define GEMM_THR 128

template <int ADDI, int TRI, int BETAHL, int ZB, int FPOUT, int HLOUT, int F16M>
__global__ void __launch_bounds__(GEMM_THR, 2)
mma_gemm(const __nv_bfloat16* __restrict__ A, const __nv_bfloat16* __restrict__ B,
         float* __restrict__ C, void* __restrict__ Chl,
         const __nv_bfloat16* __restrict__ Cin,
         int K, int lda2, int loA, int ldb2, int loB,
         int ldc, int ldchl, float alpha, float rbeta,
         long long zAs, long long zBs, long long zCHs, int M0, int dM)
{
    extern __shared__ __align__(128) char smem[];
    const uint32_t s0 = smem_u32(smem);
    const int tid  = threadIdx.x;
    const int lane = tid & 31;
    const int wid  = tid >> 5;
    const int wm   = wid >> 1;
    const int wn   = wid & 1;

    if (ZB) {
        const int z = blockIdx.z;
        A += zAs * z; B += zBs * z;
        if (HLOUT || F16M) Chl = (void*)((char*)Chl + zCHs * 2 * (long long)z);
        if ((int)(blockIdx.y * 128) >= M0 - dM * z) return;
    }

    int row0, col0;
    if (TRI) {
        int bid = blockIdx.x;
        int r = 0;
        while ((r + 1) * (r + 2) / 2 <= bid) ++r;
        row0 = r * 128;
        col0 = (bid - r * (r + 1) / 2) * 128;
    } else {
        row0 = blockIdx.y * 128;
        col0 = blockIdx.x * 128;
    }

    const int T = K / 32;

    float acc[4][8][4];
#pragma unroll
    for (int i = 0; i < 4; i++)
#pragma unroll
        for (int j = 0; j < 8; j++)
#pragma unroll
            for (int q = 0; q < 4; q++) acc[i][j][q] = 0.f;

    auto load_stage = [&](int s) {
        const int k0 = s * 32;
        const uint32_t base = s0 + (s % 3) * STAGE_B;
#pragma unroll
        for (int qq = 0; qq < 4; ++qq) {
            const int jj = tid + qq * GEMM_THR;
            const int r  = jj >> 2;
            const int cc = jj & 3;
            const uint32_t soff = r * 64 + ((cc ^ ((r >> 1) & 3)) << 4);
            const __nv_bfloat16* ag = A + (size_t)(row0 + r) * lda2 + k0 + cc * 8;
            const __nv_bfloat16* bg = B + (size_t)(col0 + r) * ldb2 + k0 + cc * 8;
            cpa16(base + 0 * TILE_B + soff, ag);
            cpa16(base + 1 * TILE_B + soff, ag + loA);
            cpa16(base + 2 * TILE_B + soff, bg);
            cpa16(base + 3 * TILE_B + soff, bg + loB);
        }
        CPA_COMMIT();
    };

    load_stage(0); load_stage(1);

    for (int s = 0; s < T; ++s) {
        CPA_WAIT(1);
        __syncthreads();
        if (s + 2 < T) load_stage(s + 2);

        const uint32_t buf = s0 + (s % 3) * STAGE_B;
#pragma unroll
        for (int kk = 0; kk < 2; ++kk) {
            uint32_t ah[4][4], al[4][4], bb[8][2];
#pragma unroll
            for (int mi = 0; mi < 4; ++mi) {
                const int row = wm * 64 + mi * 16 + ((lane >> 3) & 1) * 8 + (lane & 7);
                const int cc  = kk * 2 + (lane >> 4);
                const uint32_t off = row * 64 + ((cc ^ ((row >> 1) & 3)) << 4);
                LDSM4(ah[mi][0], ah[mi][1], ah[mi][2], ah[mi][3], buf + 0 * TILE_B + off);
                LDSM4(al[mi][0], al[mi][1], al[mi][2], al[mi][3], buf + 1 * TILE_B + off);
            }
#pragma unroll
            for (int p = 0; p < 4; ++p) {
                const int row = wn * 64 + p * 16 + (lane >> 4) * 8 + (lane & 7);
                const int cc  = kk * 2 + ((lane >> 3) & 1);
                const uint32_t off = row * 64 + ((cc ^ ((row >> 1) & 3)) << 4);
                LDSM4(bb[p * 2][0], bb[p * 2][1], bb[p * 2 + 1][0], bb[p * 2 + 1][1],
                      buf + 2 * TILE_B + off);
            }
#pragma unroll
            for (int mi = 0; mi < 4; ++mi)
#pragma unroll
                for (int nj = 0; nj < 8; ++nj) {
                    MMA16816(acc[mi][nj], ah[mi], bb[nj][0], bb[nj][1]);  // hh
                    MMA16816(acc[mi][nj], al[mi], bb[nj][0], bb[nj][1]);  // lh
                }
#pragma unroll
            for (int p = 0; p < 4; ++p) {
                const int row = wn * 64 + p * 16 + (lane >> 4) * 8 + (lane & 7);
                const int cc  = kk * 2 + ((lane >> 3) & 1);
                const uint32_t off = row * 64 + ((cc ^ ((row >> 1) & 3)) << 4);
                LDSM4(bb[p * 2][0], bb[p * 2][1], bb[p * 2 + 1][0], bb[p * 2 + 1][1],
                      buf + 3 * TILE_B + off);
            }
#pragma unroll
            for (int mi = 0; mi < 4; ++mi)
#pragma unroll
                for (int nj = 0; nj < 8; ++nj)
                    MMA16816(acc[mi][nj], ah[mi], bb[nj][0], bb[nj][1]);  // hl
        }
    }

    const int g = lane >> 2, t = lane & 3;
    const int half = ldchl >> 1;
#pragma unroll
    for (int mi = 0; mi < 4; ++mi) {
#pragma unroll
        for (int nj = 0; nj < 8; ++nj) {
            const int r_ = row0 + wm * 64 + mi * 16 + g;
            const int c_ = col0 + wn * 64 + nj * 8 + 2 * t;
            float2 v, v2;
            v.x  = alpha * acc[mi][nj][0];
            v.y  = alpha * acc[mi][nj][1];
            v2.x = alpha * acc[mi][nj][2];
            v2.y = alpha * acc[mi][nj][3];
            if (BETAHL) {
                __nv_bfloat162 ih  = *reinterpret_cast<const __nv_bfloat162*>(
                    &Cin[(size_t)r_ * ldchl + c_]);
                __nv_bfloat162 il  = *reinterpret_cast<const __nv_bfloat162*>(
                    &Cin[(size_t)r_ * ldchl + half + c_]);
                __nv_bfloat162 ih2 = *reinterpret_cast<const __nv_bfloat162*>(
                    &Cin[(size_t)(r_ + 8) * ldchl + c_]);
                __nv_bfloat162 il2 = *reinterpret_cast<const __nv_bfloat162*>(
                    &Cin[(size_t)(r_ + 8) * ldchl + half + c_]);
                v.x  += rbeta * (__bfloat162float(ih.x)  + __bfloat162float(il.x));
                v.y  += rbeta * (__bfloat162float(ih.y)  + __bfloat162float(il.y));
                v2.x += rbeta * (__bfloat162float(ih2.x) + __bfloat162float(il2.x));
                v2.y += rbeta * (__bfloat162float(ih2.y) + __bfloat162float(il2.y));
            }
            if (ADDI) {
                if (r_ == c_)     v.x  += 1.f;
                if (r_ == c_ + 1) v.y  += 1.f;
                if (r_ + 8 == c_)     v2.x += 1.f;
                if (r_ + 8 == c_ + 1) v2.y += 1.f;
            }
            if (FPOUT) {
                *reinterpret_cast<float2*>(&C[(size_t)r_ * ldc + c_])       = v;
                *reinterpret_cast<float2*>(&C[(size_t)(r_ + 8) * ldc + c_]) = v2;
            }
            if (HLOUT) {
                __nv_bfloat16* Cb = (__nv_bfloat16*)Chl;
                __nv_bfloat162 h, h2, l, l2;
                h.x  = __float2bfloat16(v.x);   h.y  = __float2bfloat16(v.y);
                h2.x = __float2bfloat16(v2.x);  h2.y = __float2bfloat16(v2.y);
                l.x  = __float2bfloat16(v.x  - __bfloat162float(h.x));
                l.y  = __float2bfloat16(v.y  - __bfloat162float(h.y));
                l2.x = __float2bfloat16(v2.x - __bfloat162float(h2.x));
                l2.y = __float2bfloat16(v2.y - __bfloat162float(h2.y));
                *reinterpret_cast<__nv_bfloat162*>(&Cb[(size_t)r_ * ldchl + c_])              = h;
                *reinterpret_cast<__nv_bfloat162*>(&Cb[(size_t)r_ * ldchl + half + c_])       = l;
                *reinterpret_cast<__nv_bfloat162*>(&Cb[(size_t)(r_ + 8) * ldchl + c_])        = h2;
                *reinterpret_cast<__nv_bfloat162*>(&Cb[(size_t)(r_ + 8) * ldchl + half + c_]) = l2;
            }
            if (F16M == 1) {
                __half* Ch = (__half*)Chl;
                *reinterpret_cast<__half2*>(&Ch[(size_t)r_ * ldchl + c_]) =
                    __floats2half2_rn(v.x, v.y);
                *reinterpret_cast<__half2*>(&Ch[(size_t)(r_ + 8) * ldchl + c_]) =
                    __floats2half2_rn(v2.x, v2.y);
            }
            if (F16M == 2) {
                __half* Ch = (__half*)Chl;
                __half2 h  = __floats2half2_rn(v.x,  v.y);
                __half2 h2 = __floats2half2_rn(v2.x, v2.y);
                __half2 l  = __floats2half2_rn(v.x  - __half2float(h.x),
                                               v.y  - __half2float(h.y));
                __half2 l2 = __floats2half2_rn(v2.x - __half2float(h2.x),
                                               v2.y - __half2float(h2.y));
                *reinterpret_cast<__half2*>(&Ch[(size_t)r_ * ldchl + c_])              = h;
                *reinterpret_cast<__half2*>(&Ch[(size_t)r_ * ldchl + half + c_])       = l;
                *reinterpret_cast<__half2*>(&Ch[(size_t)(r_ + 8) * ldchl + c_])        = h2;
                *reinterpret_cast<__half2*>(&Ch[(size_t)(r_ + 8) * ldchl + half + c_]) = l2;
            }
        }
    }
}

// ============================================================================
// fp16 single-product GEMM (out = P @ X): K=64 per stage, 128B-row swizzle.
// ============================================================================
#define TILE_H   16384
#define STAGE_H  (2 * TILE_H)
#define GEMMH_SMEM (3 * STAGE_H)

__global__ void __launch_bounds__(GEMM_THR, 2)
mma_gemm_h(const __half* __restrict__ A, const __half* __restrict__ B,
           float* __restrict__ C, int K, int lda, int ldb, int ldc)
{
    extern __shared__ __align__(128) char smem[];
    const uint32_t s0 = smem_u32(smem);
    const int tid  = threadIdx.x;
    const int lane = tid & 31;
    const int wid  = tid >> 5;
    const int wm   = wid >> 1;
    const int wn   = wid & 1;
    const int row0 = blockIdx.y * 128;
    const int col0 = blockIdx.x * 128;
    const int T = K / 64;

    float acc[4][8][4];
#pragma unroll
    for (int i = 0; i < 4; i++)
#pragma unroll
        for (int j = 0; j < 8; j++)
#pragma unroll
            for (int q = 0; q < 4; q++) acc[i][j][q] = 0.f;

    auto load_stage = [&](int s) {
        const int k0 = s * 64;
        const uint32_t base = s0 + (s % 3) * STAGE_H;
#pragma unroll
        for (int qq = 0; qq < 8; ++qq) {
            const int jj = tid + qq * GEMM_THR;
            const int r  = jj >> 3;
            const int cc = jj & 7;
            const uint32_t soff = r * 128 + ((cc ^ (r & 7)) << 4);
            cpa16(base + soff,          A + (size_t)(row0 + r) * lda + k0 + cc * 8);
            cpa16(base + TILE_H + soff, B + (size_t)(col0 + r) * ldb + k0 + cc * 8);
        }
        CPA_COMMIT();
    };

    load_stage(0); load_stage(1);

    for (int s = 0; s < T; ++s) {
        CPA_WAIT(1);
        __syncthreads();
        if (s + 2 < T) load_stage(s + 2);

        const uint32_t buf = s0 + (s % 3) * STAGE_H;
#pragma unroll
        for (int kk = 0; kk < 4; ++kk) {
            uint32_t ah[4][4], bb[8][2];
#pragma unroll
            for (int mi = 0; mi < 4; ++mi) {
                const int row = wm * 64 + mi * 16 + ((lane >> 3) & 1) * 8 + (lane & 7);
                const int cc  = kk * 2 + (lane >> 4);
                const uint32_t off = row * 128 + ((cc ^ (row & 7)) << 4);
                LDSM4(ah[mi][0], ah[mi][1], ah[mi][2], ah[mi][3], buf + off);
            }
#pragma unroll
            for (int p = 0; p < 4; ++p) {
                const int row = wn * 64 + p * 16 + (lane >> 4) * 8 + (lane & 7);
                const int cc  = kk * 2 + ((lane >> 3) & 1);
                const uint32_t off = row * 128 + ((cc ^ (row & 7)) << 4);
                LDSM4(bb[p * 2][0], bb[p * 2][1], bb[p * 2 + 1][0], bb[p * 2 + 1][1],
                      buf + TILE_H + off);
            }
#pragma unroll
            for (int mi = 0; mi < 4; ++mi)
#pragma unroll
                for (int nj = 0; nj < 8; ++nj)
                    MMA16816H(acc[mi][nj], ah[mi], bb[nj][0], bb[nj][1]);
        }
    }

    const int g = lane >> 2, t = lane & 3;
#pragma unroll
    for (int mi = 0; mi < 4; ++mi) {
#pragma unroll
        for (int nj = 0; nj < 8; ++nj) {
            const int r_ = row0 + wm * 64 + mi * 16 + g;
            const int c_ = col0 + wn * 64 + nj * 8 + 2 * t;
            *reinterpret_cast<float2*>(&C[(size_t)r_ * ldc + c_]) =
                make_float2(acc[mi][nj][0], acc[mi][nj][1]);
            *reinterpret_cast<float2*>(&C[(size_t)(r_ + 8) * ldc + c_]) =
                make_float2(acc[mi][nj][2], acc[mi][nj][3]);
        }
    }
}

// ============================================================================
// fp16 2-product GEMM for P = I - A @ B^T:
//   A: [M, 2K] fp16 (hi | lo).  B: [N, K] fp16 single.  Out: fp16 P.
// ============================================================================
#define TILE_P 8192
#define STAGE_P (3 * TILE_P)
#define GEMMP_SMEM (3 * STAGE_P)

__global__ void __launch_bounds__(GEMM_THR, 2)
p_gemm_h2(const __half* __restrict__ A, const __half* __restrict__ B,
          __half* __restrict__ P, int K, int lda2, int loA, int ldb, int ldp)
{
    extern __shared__ __align__(128) char smem[];
    const uint32_t s0 = smem_u32(smem);
    const int tid  = threadIdx.x;
    const int lane = tid & 31;
    const int wid  = tid >> 5;
    const int wm   = wid >> 1;
    const int wn   = wid & 1;
    const int row0 = blockIdx.y * 128;
    const int col0 = blockIdx.x * 128;
    const int T = K / 32;

    float acc[4][8][4];
#pragma unroll
    for (int i = 0; i < 4; i++)
#pragma unroll
        for (int j = 0; j < 8; j++)
#pragma unroll
            for (int q = 0; q < 4; q++) acc[i][j][q] = 0.f;

    auto load_stage = [&](int s) {
        const int k0 = s * 32;
        const uint32_t base = s0 + (s % 3) * STAGE_P;
#pragma unroll
        for (int qq = 0; qq < 4; ++qq) {
            const int jj = tid + qq * GEMM_THR;
            const int r  = jj >> 2;
            const int cc = jj & 3;
            const uint32_t soff = r * 64 + ((cc ^ ((r >> 1) & 3)) << 4);
            const __half* ag = A + (size_t)(row0 + r) * lda2 + k0 + cc * 8;
            cpa16(base + 0 * TILE_P + soff, ag);
            cpa16(base + 1 * TILE_P + soff, ag + loA);
            cpa16(base + 2 * TILE_P + soff,
                  B + (size_t)(col0 + r) * ldb + k0 + cc * 8);
        }
        CPA_COMMIT();
    };

    load_stage(0); load_stage(1);

    for (int s = 0; s < T; ++s) {
        CPA_WAIT(1);
        __syncthreads();
        if (s + 2 < T) load_stage(s + 2);

        const uint32_t buf = s0 + (s % 3) * STAGE_P;
#pragma unroll
        for (int kk = 0; kk < 2; ++kk) {
            uint32_t ah[4][4], al[4][4], bb[8][2];
#pragma unroll
            for (int mi = 0; mi < 4; ++mi) {
                const int row = wm * 64 + mi * 16 + ((lane >> 3) & 1) * 8 + (lane & 7);
                const int cc  = kk * 2 + (lane >> 4);
                const uint32_t off = row * 64 + ((cc ^ ((row >> 1) & 3)) << 4);
                LDSM4(ah[mi][0], ah[mi][1], ah[mi][2], ah[mi][3], buf + 0 * TILE_P + off);
                LDSM4(al[mi][0], al[mi][1], al[mi][2], al[mi][3], buf + 1 * TILE_P + off);
            }
#pragma unroll
            for (int p = 0; p < 4; ++p) {
                const int row = wn * 64 + p * 16 + (lane >> 4) * 8 + (lane & 7);
                const int cc  = kk * 2 + ((lane >> 3) & 1);
                const uint32_t off = row * 64 + ((cc ^ ((row >> 1) & 3)) << 4);
                LDSM4(bb[p * 2][0], bb[p * 2][1], bb[p * 2 + 1][0], bb[p * 2 + 1][1],
                      buf + 2 * TILE_P + off);
            }
#pragma unroll
            for (int mi = 0; mi < 4; ++mi)
#pragma unroll
                for (int nj = 0; nj < 8; ++nj) {
                    MMA16816H(acc[mi][nj], ah[mi], bb[nj][0], bb[nj][1]);
                    MMA16816H(acc[mi][nj], al[mi], bb[nj][0], bb[nj][1]);
                }
        }
    }

    const int g = lane >> 2, t = lane & 3;
#pragma unroll
    for (int mi = 0; mi < 4; ++mi) {
#pragma unroll
        for (int nj = 0; nj < 8; ++nj) {
            const int r_ = row0 + wm * 64 + mi * 16 + g;
            const int c_ = col0 + wn * 64 + nj * 8 + 2 * t;
            float2 v, v2;
            v.x  = -acc[mi][nj][0];
            v.y  = -acc[mi][nj][1];
            v2.x = -acc[mi][nj][2];
            v2.y = -acc[mi][nj][3];
            if (r_ == c_)     v.x  += 1.f;
            if (r_ == c_ + 1) v.y  += 1.f;
            if (r_ + 8 == c_)     v2.x += 1.f;
            if (r_ + 8 == c_ + 1) v2.y += 1.f;
            *reinterpret_cast<__half2*>(&P[(size_t)r_ * ldp + c_]) =
                __floats2half2_rn(v.x, v.y);
            *reinterpret_cast<__half2*>(&P[(size_t)(r_ + 8) * ldp + c_]) =
                __floats2half2_rn(v2.x, v2.y);
        }
    }
}

// ============================================================================
// Row-normalize U -> Vn (fp32) + Vn_hl
// ============================================================================
__global__ void normalize_kernel(const float* __restrict__ U) {
    int row = blockIdx.x;
    const float* u = U + (size_t)row * D_DIM;
    __shared__ float red[256];
    float s = 0.f;
    for (int c = threadIdx.x; c < D_DIM; c += 256) { float v = u[c]; s += v * v; }
    red[threadIdx.x] = s;
    __syncthreads();
    for (int off = 128; off > 0; off >>= 1) {
        if (threadIdx.x < off) red[threadIdx.x] += red[threadIdx.x + off];
        __syncthreads();
    }
    float inv = rsqrtf(red[0]);
    for (int c = threadIdx.x; c < D_DIM; c += 256) {
        float v = u[c] * inv;
        g_Vn[(size_t)row * D_DIM + c] = v;
        __nv_bfloat16 h = __float2bfloat16(v);
        g_Vn_hl[(size_t)row * 2 * D_DIM + c]         = h;
        g_Vn_hl[(size_t)row * 2 * D_DIM + D_DIM + c] =
            __float2bfloat16(v - __bfloat162float(h));
    }
}

// ============================================================================
// conversions
// ============================================================================
__global__ void conv_hl_T_gen(const float* __restrict__ in, int R, int C,
                              __nv_bfloat16* __restrict__ out, int outld,
                              int outcol0, int looff,
                              long long zIn, long long zOut) {
    in  += zIn  * blockIdx.z;
    out += zOut * blockIdx.z;
    __shared__ float t[32][33];
    int r0 = blockIdx.y * 32, c0 = blockIdx.x * 32;
    int tx = threadIdx.x, ty = threadIdx.y;
    for (int i = 0; i < 32; i += 8)
        t[ty + i][tx] = in[(size_t)(r0 + ty + i) * C + c0 + tx];
    __syncthreads();
    for (int i = 0; i < 32; i += 8) {
        float x = t[tx][ty + i];
        __nv_bfloat16 h = __float2bfloat16(x);
        out[(size_t)(c0 + ty + i) * outld + outcol0 + r0 + tx] = h;
        out[(size_t)(c0 + ty + i) * outld + looff + outcol0 + r0 + tx] =
            __float2bfloat16(x - __bfloat162float(h));
    }
}
// Vn transpose: emits bf16 hi/lo (VnT_hl) AND fp16 single (VnT_h)
__global__ void conv_T_vn(const float* __restrict__ in) {
    __shared__ float t[32][33];
    int r0 = blockIdx.y * 32, c0 = blockIdx.x * 32;
    int tx = threadIdx.x, ty = threadIdx.y;
    for (int i = 0; i < 32; i += 8)
        t[ty + i][tx] = in[(size_t)(r0 + ty + i) * D_DIM + c0 + tx];
    __syncthreads();
    for (int i = 0; i < 32; i += 8) {
        float x = t[tx][ty + i];
        __nv_bfloat16 h = __float2bfloat16(x);
        size_t ro = (size_t)(c0 + ty + i);
        g_VnT_hl[ro * 2 * D_DIM + r0 + tx]         = h;
        g_VnT_hl[ro * 2 * D_DIM + D_DIM + r0 + tx] =
            __float2bfloat16(x - __bfloat162float(h));
        g_VnT_h [ro * D_DIM + r0 + tx] = __float2half(x);
    }
}
__global__ void conv_h_T(const float* __restrict__ in, int R, int C,
                         __half* __restrict__ out, int outld) {
    __shared__ float t[32][33];
    int r0 = blockIdx.y * 32, c0 = blockIdx.x * 32;
    int tx = threadIdx.x, ty = threadIdx.y;
    for (int i = 0; i < 32; i += 8)
        t[ty + i][tx] = in[(size_t)(r0 + ty + i) * C + c0 + tx];
    __syncthreads();
    for (int i = 0; i < 32; i += 8)
        out[(size_t)(c0 + ty + i) * outld + r0 + tx] = __float2half(t[tx][ty + i]);
}
// Seed RHST_hl block 0 = 2 * VnT_hl block 0 (exact, power of 2)
__global__ void seed_rhst0() {
    int r = blockIdx.x;
    int c = threadIdx.x;
    size_t base = (size_t)r * 2 * D_DIM;
    g_RHST_hl[base + c] =
        __float2bfloat16(2.f * __bfloat162float(g_VnT_hl[base + c]));
    g_RHST_hl[base + D_DIM + c] =
        __float2bfloat16(2.f * __bfloat162float(g_VnT_hl[base + D_DIM + c]));
}

// ============================================================================
// Diag-block inversion, column-sliced (NBLK, 8) + 8-column band rounds.
// ============================================================================
#define INV_SMEM ((128 * 129 + 128 * 17) * (int)sizeof(float))
__global__ void invert_diag_kernel() {
    extern __shared__ float sm[];
    float (*Gs)[129] = (float (*)[129])sm;
    float (*Zs)[17]  = (float (*)[17])(sm + 128 * 129);
    const int b0 = blockIdx.x * NB;
    const int c0 = blockIdx.y * 16;
    const int tid = threadIdx.x;

    for (int idx = tid; idx < 128 * 128; idx += 256) {
        int r = idx >> 7, c = idx & 127;
        Gs[r][c] = g_G[(size_t)(b0 + r) * D_DIM + b0 + c];
    }
    for (int idx = tid; idx < 128 * 16; idx += 256) {
        int r = idx >> 4, c = idx & 15;
        Zs[r][c] = (r == c0 + c) ? 1.f : 0.f;
    }
    __syncthreads();

    for (int j = 0; j < NB; j += 8) {
        if (tid < 32) {
            const int c  = tid & 15;
            const int rg = tid >> 4;
#pragma unroll
            for (int q = 0; q < 7; ++q) {
                float zq = Zs[j + q][c];
#pragma unroll
                for (int rr = 0; rr < 4; ++rr) {
                    int r = rg * 4 + rr;
                    if (r > q)
                        Zs[j + r][c] -= 2.f * Gs[j + r][j + q] * zq;
                }
                __syncwarp();
            }
        }
        __syncthreads();
        const int rows = NB - 8 - j;
        for (int idx = tid; idx < rows * 16; idx += 256) {
            const int r = j + 8 + (idx >> 4);
            const int c = idx & 15;
            float acc = Zs[r][c];
#pragma unroll
            for (int q = 0; q < 8; ++q)
                acc -= 2.f * Gs[r][j + q] * Zs[j + q][c];
            Zs[r][c] = acc;
        }
        __syncthreads();
    }

    float* outp = g_Tinv + (size_t)blockIdx.x * NB * NB;
    for (int idx = tid; idx < 128 * 16; idx += 256) {
        int r = idx >> 4, c = idx & 15;
        outp[(size_t)r * NB + c0 + c] = Zs[r][c];
    }
}

// ============================================================================
// Pair-combine: 7 Tinv2 blocks (256x256) fp32 + fused row-major hi/lo split.
// ============================================================================
#define CMB_SMEM (3 * 128 * 129 * (int)sizeof(float))
__device__ __forceinline__ void cmb_wr_hl(__nv_bfloat16* Thl, int r, int c, float x) {
    __nv_bfloat16 h = __float2bfloat16(x);
    Thl[(size_t)r * 512 + c]       = h;
    Thl[(size_t)r * 512 + 256 + c] = __float2bfloat16(x - __bfloat162float(h));
}
__global__ void __launch_bounds__(256, 1) combine_tinv() {
    extern __shared__ float sm[];
    float (*Abuf)[129] = (float (*)[129])sm;
    float (*Bbuf)[129] = (float (*)[129])(sm + 128 * 129);
    float (*Tm)[129]   = (float (*)[129])(sm + 2 * 128 * 129);
    const int p = blockIdx.x;
    const int tid = threadIdx.x;
    const int trow = (tid / 16) * 8;
    const int tcol = (tid % 16) * 8;
    const float* InvA = g_Tinv + (size_t)(2 * p)     * NB * NB;
    const float* InvB = g_Tinv + (size_t)(2 * p + 1) * NB * NB;
    const size_t g21 = (size_t)(p * 256 + 128) * D_DIM + p * 256;
    __nv_bfloat16* Thl = g_Tinv2_hl + (size_t)p * NB2 * 2 * NB2;

    for (int idx = tid; idx < 128 * 128; idx += 256) {
        int r = idx >> 7, c = idx & 127;
        Abuf[r][c] = 2.f * g_G[g21 + (size_t)r * D_DIM + c];
        Bbuf[r][c] = InvA[idx];
    }
    __syncthreads();
    {
        float acc[8][8];
#pragma unroll
        for (int i = 0; i < 8; i++)
#pragma unroll
            for (int j = 0; j < 8; j++) acc[i][j] = 0.f;
        for (int k = 0; k < 128; ++k) {
            float a[8], b[8];
#pragma unroll
            for (int i = 0; i < 8; i++) a[i] = Abuf[trow + i][k];
#pragma unroll
            for (int j = 0; j < 8; j++) b[j] = Bbuf[k][tcol + j];
#pragma unroll
            for (int i = 0; i < 8; i++)
#pragma unroll
                for (int j = 0; j < 8; j++) acc[i][j] += a[i] * b[j];
        }
        __syncthreads();
#pragma unroll
        for (int i = 0; i < 8; i++)
#pragma unroll
            for (int j = 0; j < 8; j++) Tm[trow + i][tcol + j] = acc[i][j];
    }
    __syncthreads();
    for (int idx = tid; idx < 128 * 128; idx += 256) {
        int r = idx >> 7, c = idx & 127;
        Abuf[r][c] = InvB[idx];
    }
    __syncthreads();
    float* outp = g_Tinv2 + (size_t)p * NB2 * NB2;
    {
        float acc[8][8];
#pragma unroll
        for (int i = 0; i < 8; i++)
#pragma unroll
            for (int j = 0; j < 8; j++) acc[i][j] = 0.f;
        for (int k = 0; k < 128; ++k) {
            float a[8], b[8];
#pragma unroll
            for (int i = 0; i < 8; i++) a[i] = Abuf[trow + i][k];
#pragma unroll
            for (int j = 0; j < 8; j++) b[j] = Tm[k][tcol + j];
#pragma unroll
            for (int i = 0; i < 8; i++)
#pragma unroll
                for (int j = 0; j < 8; j++) acc[i][j] += a[i] * b[j];
        }
#pragma unroll
        for (int i = 0; i < 8; i++) {
#pragma unroll
            for (int j = 0; j < 8; j++) {
                int r = trow + i, c = tcol + j;
                float q21 = -acc[i][j];
                outp[(size_t)(128 + r) * NB2 + c] = q21;
                cmb_wr_hl(Thl, 128 + r, c, q21);
            }
        }
    }
    for (int idx = tid; idx < 128 * 128; idx += 256) {
        int r = idx >> 7, c = idx & 127;
        float q11 = Bbuf[r][c];
        float q22 = Abuf[r][c];
        outp[(size_t)r * NB2 + c]               = q11;
        outp[(size_t)r * NB2 + 128 + c]         = 0.f;
        outp[(size_t)(128 + r) * NB2 + 128 + c] = q22;
        cmb_wr_hl(Thl, r, c, q11);
        cmb_wr_hl(Thl, r, 128 + c, 0.f);
        cmb_wr_hl(Thl, 128 + r, 128 + c, q22);
    }
}

// ============================================================================
extern "C" void kernel_launch(void* const* d_in, const int* in_sizes, int n_in,
                              void* d_out, int out_size)
{
    const float* X;
    const float* U;
    if (in_sizes[0] == D_DIM * D_DIM && in_sizes[1] != D_DIM * D_DIM) {
        U = (const float*)d_in[0]; X = (const float*)d_in[1];
    } else {
        X = (const float*)d_in[0]; U = (const float*)d_in[1];
    }
    float* out = (float*)d_out;

    float *Vn, *G, *Tinv2;
    cudaGetSymbolAddress((void**)&Vn,    g_Vn);
    cudaGetSymbolAddress((void**)&G,     g_G);
    cudaGetSymbolAddress((void**)&Tinv2, g_Tinv2);
    __nv_bfloat16 *Vn_hl, *VnT_hl, *G_hl, *RHST_hl;
    __nv_bfloat16 *Tinv2_hl, *Tinv2T_hl, *S_hl;
    __half *P_h, *XT_h, *WtT_h2, *VnT_h;
    cudaGetSymbolAddress((void**)&Vn_hl,     g_Vn_hl);
    cudaGetSymbolAddress((void**)&VnT_hl,    g_VnT_hl);
    cudaGetSymbolAddress((void**)&G_hl,      g_G_hl);
    cudaGetSymbolAddress((void**)&RHST_hl,   g_RHST_hl);
    cudaGetSymbolAddress((void**)&Tinv2_hl,  g_Tinv2_hl);
    cudaGetSymbolAddress((void**)&Tinv2T_hl, g_Tinv2T_hl);
    cudaGetSymbolAddress((void**)&S_hl,      g_S_hl);
    cudaGetSymbolAddress((void**)&P_h,       g_P_h);
    cudaGetSymbolAddress((void**)&XT_h,      g_XT_h);
    cudaGetSymbolAddress((void**)&WtT_h2,    g_WtT_h2);
    cudaGetSymbolAddress((void**)&VnT_h,     g_VnT_h);

    cudaFuncSetAttribute(invert_diag_kernel,
                         cudaFuncAttributeMaxDynamicSharedMemorySize, INV_SMEM);
    cudaFuncSetAttribute(combine_tinv,
                         cudaFuncAttributeMaxDynamicSharedMemorySize, CMB_SMEM);
    cudaFuncSetAttribute(mma_gemm<0,1,0,0,1,1,0>,
                         cudaFuncAttributeMaxDynamicSharedMemorySize, GEMM_SMEM);
    cudaFuncSetAttribute(mma_gemm<0,0,0,1,0,1,0>,
                         cudaFuncAttributeMaxDynamicSharedMemorySize, GEMM_SMEM);
    cudaFuncSetAttribute(mma_gemm<0,0,1,0,0,1,0>,
                         cudaFuncAttributeMaxDynamicSharedMemorySize, GEMM_SMEM);
    cudaFuncSetAttribute(mma_gemm<0,0,0,1,0,0,2>,
                         cudaFuncAttributeMaxDynamicSharedMemorySize, GEMM_SMEM);
    cudaFuncSetAttribute(p_gemm_h2,
                         cudaFuncAttributeMaxDynamicSharedMemorySize, GEMMP_SMEM);
    cudaFuncSetAttribute(mma_gemm_h,
                         cudaFuncAttributeMaxDynamicSharedMemorySize, GEMMH_SMEM);

    const dim3 t32x8(32, 8);
    const int D2 = 2 * D_DIM;   // 3584

    // 0) Vn (+hl fused)
    normalize_kernel<<<D_DIM, 256>>>(U);
    // 1) VnT: bf16 hi/lo + fp16 single (fused)
    conv_T_vn<<<dim3(D_DIM / 32, D_DIM / 32), t32x8>>>(Vn);
    // 2) G = Vn @ Vn^T (lower tiles; fp32 + hl fused)
    mma_gemm<0,1,0,0,1,1,0><<<NBLK * (NBLK + 1) / 2, GEMM_THR, GEMM_SMEM>>>(
        Vn_hl, Vn_hl, G, G_hl, nullptr,
        D_DIM, D2, D_DIM, D2, D_DIM, D_DIM, D2, 1.f, 0.f, 0, 0, 0, D_DIM, 0);
    // 3) invert 14 diag blocks (column-sliced, 8-col band rounds)
    invert_diag_kernel<<<dim3(NBLK, 8), 256, INV_SMEM>>>();
    // 4) combine into 7 Tinv2 blocks (fp32 + Tinv2_hl fused)
    combine_tinv<<<NBLK2, 256, CMB_SMEM>>>();
    // 4b) Tinv2T_hl (transposed hi/lo split from fp32)
    conv_hl_T_gen<<<dim3(NB2 / 32, NB2 / 32, NBLK2), t32x8>>>(
        Tinv2, NB2, NB2, Tinv2T_hl, 2 * NB2, 0, NB2,
        (long long)NB2 * NB2, (long long)NB2 * 2 * NB2);
    // 5) S_i = 2 * G[(i+1)*256:, blk i] @ Tinv2_i^T  (z-batched, hl out)
    mma_gemm<0,0,0,1,0,1,0><<<dim3(NB2 / 128, MREM0 / 128, NBLK2 - 1), GEMM_THR, GEMM_SMEM>>>(
        G_hl + (size_t)NB2 * D2, Tinv2T_hl, nullptr, S_hl, nullptr,
        NB2, D2, D_DIM, 2 * NB2, NB2, 0, 2 * NB2, 2.f, 0.f,
        (long long)NB2 * D2 + NB2,
        (long long)NB2 * 2 * NB2,
        (long long)MREM0 * 2 * NB2,
        MREM0, NB2);
    // 5b) seed RHST_hl block 0
    seed_rhst0<<<D_DIM, 256>>>();

    // 6) transposed chain
    for (int i = 0; i < NBLK2 - 1; ++i) {
        int mrem = D_DIM - (i + 1) * NB2;
        const __nv_bfloat16* Cin = (i == 0) ? (VnT_hl + NB2) : (RHST_hl + (i + 1) * NB2);
        float rbeta = (i == 0) ? 2.f : 1.f;
        mma_gemm<0,0,1,0,0,1,0><<<dim3(mrem / 128, D_DIM / 128), GEMM_THR, GEMM_SMEM>>>(
            RHST_hl + (size_t)i * NB2,
            S_hl + (size_t)i * MREM0 * 2 * NB2,
            nullptr, RHST_hl + (i + 1) * NB2, Cin,
            NB2, D2, D_DIM, 2 * NB2, NB2, 0, D2, -1.f, rbeta,
            0, 0, 0, D_DIM, 0);
    }

    // 7) WtT(:, bi) = RHST(:, bi) @ Tinv2_bi^T — fp16 hi/lo out (z-batched)
    mma_gemm<0,0,0,1,0,0,2><<<dim3(NB2 / 128, D_DIM / 128, NBLK2), GEMM_THR, GEMM_SMEM>>>(
        RHST_hl, Tinv2_hl, nullptr, WtT_h2, nullptr,
        NB2, D2, D_DIM, 2 * NB2, NB2, 0, D2, 1.f, 0.f,
        (long long)NB2,
        (long long)NB2 * 2 * NB2,
        (long long)NB2,
        D_DIM, 0);

    // 8) P = I - WtT @ VnT-rows  (fp16 2-product, fp16 out)
    p_gemm_h2<<<dim3(D_DIM / 128, D_DIM / 128), GEMM_THR, GEMMP_SMEM>>>(
        WtT_h2, VnT_h, P_h, D_DIM, D2, D_DIM, D_DIM, D_DIM);

    // 9) X^T fp16
    conv_h_T<<<dim3(B_DIM / 32, D_DIM / 32), t32x8>>>(X, D_DIM, B_DIM, XT_h, D_DIM);

    // 10) out = P @ X
    mma_gemm_h<<<dim3(B_DIM / 128, D_DIM / 128), GEMM_THR, GEMMH_SMEM>>>(
        P_h, XT_h, out, D_DIM, D_DIM, D_DIM, B_DIM);

    (void)n_in; (void)out_size;
}